// round 9
// baseline (speedup 1.0000x reference)
#include <cuda_runtime.h>
#include <math.h>

#define GAMMA 0.99f
#define TAUF  0.95f

constexpr int THREADS = 256;
constexpr int ITEMS   = 8;
constexpr int CHUNK   = THREADS * ITEMS;   // 2048
constexpr int NWARPS  = THREADS / 32;      // 8
constexpr int NB_MAX  = 65536;

// Decoupled-lookback state (device globals; no allocation allowed)
__device__ volatile int g_status[NB_MAX];   // 0=invalid 1=aggregate 2=inclusive
__device__ float4 g_agg[NB_MAX];            // block affine summary (av,bv,aa,ba)
__device__ float2 g_incl[NB_MAX];           // inclusive carry VALUE after this block
__device__ float2 g_part[NB_MAX];           // per-block (sumA, sumA2)
__device__ float2 g_normc;                  // (mean, inv_std)
__device__ unsigned int g_done = 0;         // finish counter (reset after use)

__device__ __forceinline__ float4 ident4() { return make_float4(1.f, 0.f, 1.f, 0.f); }

// lo∘hi: hi applied first (hi = farther from block p). result = f_lo(f_hi(c))
__device__ __forceinline__ float4 comp4(float4 lo, float4 hi) {
    float4 o;
    o.x = lo.x * hi.x;
    o.y = lo.y + lo.x * hi.y;
    o.z = lo.z * hi.z;
    o.w = lo.w + lo.z * hi.w;
    return o;
}

__device__ __forceinline__ float4 shfl_down4(float4 v, int d) {
    float4 o;
    o.x = __shfl_down_sync(0xffffffffu, v.x, d);
    o.y = __shfl_down_sync(0xffffffffu, v.y, d);
    o.z = __shfl_down_sync(0xffffffffu, v.z, d);
    o.w = __shfl_down_sync(0xffffffffu, v.w, d);
    return o;
}

// Inclusive SUFFIX scan within a warp: lane i -> g_i ∘ g_{i+1} ∘ ... ∘ g_31.
__device__ __forceinline__ float4 warp_suffix_scan(float4 v, int lane) {
#pragma unroll
    for (int d = 1; d < 32; d <<= 1) {
        float4 o = shfl_down4(v, d);
        if (lane + d < 32) v = comp4(v, o);
    }
    return v;
}

__device__ __forceinline__ float4 crosswarp_suffix_scan(float4 v, int lane, int n) {
#pragma unroll
    for (int d = 1; d < 32; d <<= 1) {
        if (d >= n) break;
        float4 o = shfl_down4(v, d);
        if (lane + d < n) v = comp4(v, o);
    }
    return v;
}

struct Tile {
    float rr[ITEMS];   // r
    float dd[ITEMS];   // delta
    float a1[ITEMS];   // gamma * mask
    int   nvalid;
};

__device__ __forceinline__ void load_tile(const float* __restrict__ r,
                                          const float* __restrict__ v,
                                          const int*   __restrict__ m,
                                          long s, long B, Tile& td) {
    float vv[ITEMS + 1];
    long rem = B - s;
    td.nvalid = (rem >= ITEMS) ? ITEMS : (rem > 0 ? (int)rem : 0);
    if (td.nvalid == ITEMS) {
#pragma unroll
        for (int j = 0; j < ITEMS / 4; j++) {
            float4 x = *reinterpret_cast<const float4*>(r + s + 4 * j);
            float4 y = *reinterpret_cast<const float4*>(v + s + 4 * j);
            int4  mi = *reinterpret_cast<const int4*>(m + s + 4 * j);
            td.rr[4*j+0] = x.x; td.rr[4*j+1] = x.y; td.rr[4*j+2] = x.z; td.rr[4*j+3] = x.w;
            vv[4*j+0] = y.x; vv[4*j+1] = y.y; vv[4*j+2] = y.z; vv[4*j+3] = y.w;
            td.a1[4*j+0] = GAMMA * (float)mi.x; td.a1[4*j+1] = GAMMA * (float)mi.y;
            td.a1[4*j+2] = GAMMA * (float)mi.z; td.a1[4*j+3] = GAMMA * (float)mi.w;
        }
        vv[ITEMS] = (s + ITEMS < B) ? v[s + ITEMS] : 0.f;
    } else {
#pragma unroll
        for (int i = 0; i < ITEMS; i++) {
            if (i < td.nvalid) {
                td.rr[i] = r[s + i];
                vv[i]    = v[s + i];
                td.a1[i] = GAMMA * (float)m[s + i];
            } else { td.rr[i] = 0.f; vv[i] = 0.f; td.a1[i] = 0.f; }
        }
        vv[ITEMS] = 0.f;
    }
#pragma unroll
    for (int i = 0; i < ITEMS; i++)
        td.dd[i] = td.rr[i] + td.a1[i] * vv[i + 1] - vv[i];
}

__device__ __forceinline__ float4 tile_summary(const Tile& td) {
    float av = 1.f, bv = 0.f, aa = 1.f, ba = 0.f;
#pragma unroll
    for (int i = 0; i < ITEMS; i++) {
        if (i < td.nvalid) {
            float a1 = td.a1[i];
            float a2 = a1 * TAUF;
            bv = bv + av * td.rr[i]; av = av * a1;
            ba = ba + aa * td.dd[i]; aa = aa * a2;
        }
    }
    return make_float4(av, bv, aa, ba);
}

// ---------------- single-pass scan, BLOCK-WIDE (256-wide) decoupled lookback ----------------
__global__ void __launch_bounds__(THREADS) k_scan(const float* __restrict__ r,
                                                  const float* __restrict__ v,
                                                  const int* __restrict__ m,
                                                  float* __restrict__ outA,
                                                  float* __restrict__ outVT,
                                                  long B, int NB) {
    __shared__ float4 WAGG[NWARPS];
    __shared__ float4 WEX[NWARPS];      // exclusive (nearer-warps) composition per warp
    __shared__ float4 WPROD[NWARPS];    // lookback: per-warp window product
    __shared__ int    WINC[NWARPS];     // lookback: warp window contains an inclusive
    __shared__ float4 HRUN;             // lookback running product across rounds
    __shared__ float4 FS;               // block aggregate
    __shared__ float2 CBS;              // resolved incoming carry
    __shared__ int    DONEF;
    __shared__ float2 WSUM[NWARPS];
    __shared__ int    LASTF;
    __shared__ double DS[NWARPS], DQ[NWARPS];

    int t = threadIdx.x, lane = t & 31, w = t >> 5;
    int p = blockIdx.x;                 // processing order
    int ti = NB - 1 - p;                // tile index (reverse scan -> from the end)
    long s = (long)ti * CHUNK + (long)t * ITEMS;

    Tile td;
    load_tile(r, v, m, s, B, td);
    float4 f = tile_summary(td);
    float4 sfx = warp_suffix_scan(f, lane);
    if (lane == 0) WAGG[w] = sfx;
    __syncthreads();

    if (w == 0) {
        float4 sw = (lane < NWARPS) ? WAGG[lane] : ident4();
        sw = crosswarp_suffix_scan(sw, lane, NWARPS);
        float4 ex = shfl_down4(sw, 1);
        if (lane >= NWARPS - 1) ex = ident4();
        if (lane < NWARPS) WEX[lane] = ex;
        if (lane == 0) {
            FS = sw;                                  // block aggregate
            HRUN = ident4();
            DONEF = 0;
            if (p > 0) {
                volatile float* ap = (volatile float*)&g_agg[p];
                ap[0] = sw.x; ap[1] = sw.y; ap[2] = sw.z; ap[3] = sw.w;
                __threadfence();
                g_status[p] = 1;                      // AGGREGATE available
            }
        }
    }
    __syncthreads();

    // -------- block-wide lookback: 256 predecessors per round --------
    float2 cb = make_float2(0.f, 0.f);
    if (p > 0) {
        int q = p - 1;
        for (;;) {
            int idx = q - t;                          // t=0 nearest
            int st;
            for (;;) {
                st = (idx >= 0) ? g_status[idx] : 1;
                if (!__any_sync(0xffffffffu, st == 0)) break;
                __nanosleep(20);
            }
            __threadfence();                          // acquire payloads
            bool isinc = (st == 2) && (idx >= 0);
            float4 gi;
            if (isinc) {
                volatile float* ip = (volatile float*)&g_incl[idx];
                gi = make_float4(0.f, ip[0], 0.f, ip[1]);   // constant map (absorbs right)
            } else if (idx >= 0) {
                volatile float* ap = (volatile float*)&g_agg[idx];
                gi.x = ap[0]; gi.y = ap[1]; gi.z = ap[2]; gi.w = ap[3];
            } else {
                gi = ident4();
            }
            unsigned ball = __ballot_sync(0xffffffffu, isinc);
            float4 prod = warp_suffix_scan(gi, lane); // lane0: window product (const-map absorbs)
            if (lane == 0) { WPROD[w] = prod; WINC[w] = (ball != 0); }
            __syncthreads();
            if (t == 0) {
                float4 run = HRUN;
                int done = 0;
#pragma unroll
                for (int w2 = 0; w2 < NWARPS; w2++) {
                    run = comp4(run, WPROD[w2]);
                    if (WINC[w2]) { done = 1; break; }
                }
                if (done) {
                    CBS = make_float2(run.y, run.w);  // run is a constant map now
                } else {
                    HRUN = run;
                }
                DONEF = done;
            }
            __syncthreads();
            if (DONEF) { cb = CBS; break; }
            q -= THREADS;
        }
    }
    // publish inclusive ASAP (unblocks successors)
    if (t == 0) {
        float4 F = FS;
        float incx = F.y + F.x * cb.x;
        float incy = F.w + F.z * cb.y;
        volatile float* op = (volatile float*)&g_incl[p];
        op[0] = incx;
        op[1] = incy;
        __threadfence();
        g_status[p] = 2;                              // INCLUSIVE available
    }

    // per-warp entering carry values
    float4 ex = WEX[w];
    float2 wcar;
    wcar.x = ex.y + ex.x * cb.x;
    wcar.y = ex.w + ex.z * cb.y;
    float4 X = shfl_down4(sfx, 1);
    if (lane == 31) X = ident4();
    float cvt = X.y + X.x * wcar.x;
    float ca  = X.w + X.z * wcar.y;

    float sA = 0.f, sQ = 0.f;
#pragma unroll
    for (int i = ITEMS - 1; i >= 0; i--) {
        if (i < td.nvalid) {
            float a1 = td.a1[i];
            float vt = td.rr[i] + a1 * cvt;
            float A  = td.dd[i] + a1 * TAUF * ca;
            td.rr[i] = vt;
            td.dd[i] = A;
            cvt = vt; ca = A;
            sA += A; sQ += A * A;
        }
    }
    if (td.nvalid == ITEMS) {
#pragma unroll
        for (int j2 = 0; j2 < ITEMS / 4; j2++) {
            *reinterpret_cast<float4*>(outA + s + 4 * j2) =
                make_float4(td.dd[4*j2+0], td.dd[4*j2+1], td.dd[4*j2+2], td.dd[4*j2+3]);
            *reinterpret_cast<float4*>(outVT + s + 4 * j2) =
                make_float4(td.rr[4*j2+0], td.rr[4*j2+1], td.rr[4*j2+2], td.rr[4*j2+3]);
        }
    } else {
        for (int i = 0; i < td.nvalid; i++) {
            outA[s + i]  = td.dd[i];
            outVT[s + i] = td.rr[i];
        }
    }
    // per-block stats
#pragma unroll
    for (int d = 16; d > 0; d >>= 1) {
        sA += __shfl_down_sync(0xffffffffu, sA, d);
        sQ += __shfl_down_sync(0xffffffffu, sQ, d);
    }
    if (lane == 0) WSUM[w] = make_float2(sA, sQ);
    __syncthreads();
    if (w == 0) {
        float2 pp = (lane < NWARPS) ? WSUM[lane] : make_float2(0.f, 0.f);
        float a = pp.x, q2 = pp.y;
#pragma unroll
        for (int d = NWARPS / 2; d > 0; d >>= 1) {
            a  += __shfl_down_sync(0xffffffffu, a, d);
            q2 += __shfl_down_sync(0xffffffffu, q2, d);
        }
        if (lane == 0) g_part[p] = make_float2(a, q2);
    }
    // last block to finish computes global stats (fused epilogue reduce)
    if (t == 0) {
        __threadfence();
        unsigned int dn = atomicAdd(&g_done, 1);
        LASTF = (dn == (unsigned int)NB - 1) ? 1 : 0;
    }
    __syncthreads();
    if (LASTF) {
        double sd = 0.0, qd = 0.0;
        for (int i = t; i < NB; i += THREADS) {
            float2 pp = g_part[i];
            sd += (double)pp.x; qd += (double)pp.y;
        }
#pragma unroll
        for (int d = 16; d > 0; d >>= 1) {
            sd += __shfl_down_sync(0xffffffffu, sd, d);
            qd += __shfl_down_sync(0xffffffffu, qd, d);
        }
        if (lane == 0) { DS[w] = sd; DQ[w] = qd; }
        __syncthreads();
        if (w == 0) {
            bool ok = lane < NWARPS;
            sd = ok ? DS[lane] : 0.0;
            qd = ok ? DQ[lane] : 0.0;
#pragma unroll
            for (int d = NWARPS / 2; d > 0; d >>= 1) {
                sd += __shfl_down_sync(0xffffffffu, sd, d);
                qd += __shfl_down_sync(0xffffffffu, qd, d);
            }
            if (lane == 0) {
                double mean = sd / (double)B;
                double var  = (qd - sd * mean) / (double)(B - 1);
                g_normc = make_float2((float)mean, (float)(1.0 / sqrt(var)));
                g_done = 0;                           // reset for next replay
            }
        }
    }
}

// ---------------- normalize A (L2-hot) + reset lookback flags for next replay ----------------
__global__ void __launch_bounds__(THREADS) k_norm(float* __restrict__ A, long B, int NB) {
    float2 nc = g_normc;
    float mean = nc.x, istd = nc.y;
    long n4 = B >> 2;
    long gid = (long)blockIdx.x * blockDim.x + threadIdx.x;
    long stride = (long)gridDim.x * blockDim.x;
    float4* A4 = reinterpret_cast<float4*>(A);
    for (long i = gid; i < n4; i += stride) {
        float4 x = A4[i];
        x.x = (x.x - mean) * istd;
        x.y = (x.y - mean) * istd;
        x.z = (x.z - mean) * istd;
        x.w = (x.w - mean) * istd;
        A4[i] = x;
    }
    long tail = n4 << 2;
    long j = tail + gid;
    if (j < B) A[j] = (A[j] - mean) * istd;
    // reset statuses for the next graph replay
    for (long i = gid; i < NB; i += stride) g_status[i] = 0;
}

extern "C" void kernel_launch(void* const* d_in, const int* in_sizes, int n_in,
                              void* d_out, int out_size) {
    const float* r = (const float*)d_in[0];
    const float* v = (const float*)d_in[1];
    const int*   m = (const int*)d_in[2];
    long B = (long)in_sizes[0];
    float* outA  = (float*)d_out;
    float* outVT = outA + B;

    int NB = (int)((B + CHUNK - 1) / CHUNK);
    if (NB > NB_MAX) NB = NB_MAX;   // this problem: NB = 2048

    k_scan<<<NB, THREADS>>>(r, v, m, outA, outVT, B, NB);

    long n4 = (B + 3) / 4;
    int nbn = (int)((n4 + THREADS - 1) / THREADS);
    if (nbn > 4096) nbn = 4096;
    k_norm<<<nbn, THREADS>>>(outA, B, NB);
}

// round 10
// speedup vs baseline: 1.7121x; 1.7121x over previous
#include <cuda_runtime.h>
#include <math.h>

#define GAMMA 0.99f
#define TAUF  0.95f

constexpr int THREADS = 256;
constexpr int ITEMS   = 8;
constexpr int CHUNK   = THREADS * ITEMS;   // 2048
constexpr int NWARPS  = THREADS / 32;      // 8
constexpr int PER     = 8;                 // summaries per thread in fused pass2
constexpr int NB_MAX  = THREADS * PER;     // 2048 blocks max (B <= 4,194,304)

// Scratch (device globals; no allocation allowed)
__device__ float4 g_blk[NB_MAX];     // per-block affine summary: (a_vt, b_vt, a_A, b_A)
__device__ float2 g_carry[NB_MAX];   // per-block incoming carry VALUES (vt, A)
__device__ float4 g_mA[NB_MAX];      // per-block (SP, SG, SPP, SPG)
__device__ float  g_mB[NB_MAX];      // per-block SGG
__device__ float2 g_normc;           // (mean, inv_std)
__device__ unsigned int g_done = 0;  // finish counter (reset by last block)

__device__ __forceinline__ float4 ident4() { return make_float4(1.f, 0.f, 1.f, 0.f); }

// lo covers lower (earlier) indices; carry flows high->low: result = f_lo(f_hi(c))
__device__ __forceinline__ float4 comp4(float4 lo, float4 hi) {
    float4 o;
    o.x = lo.x * hi.x;
    o.y = lo.y + lo.x * hi.y;
    o.z = lo.z * hi.z;
    o.w = lo.w + lo.z * hi.w;
    return o;
}

__device__ __forceinline__ float4 shfl_down4(float4 v, int d) {
    float4 o;
    o.x = __shfl_down_sync(0xffffffffu, v.x, d);
    o.y = __shfl_down_sync(0xffffffffu, v.y, d);
    o.z = __shfl_down_sync(0xffffffffu, v.z, d);
    o.w = __shfl_down_sync(0xffffffffu, v.w, d);
    return o;
}

// Inclusive SUFFIX scan within a warp; ALL 32 lanes execute.
__device__ __forceinline__ float4 warp_suffix_scan(float4 v, int lane) {
#pragma unroll
    for (int d = 1; d < 32; d <<= 1) {
        float4 o = shfl_down4(v, d);
        if (lane + d < 32) v = comp4(v, o);
    }
    return v;
}

__device__ __forceinline__ float4 crosswarp_suffix_scan(float4 v, int lane, int n) {
#pragma unroll
    for (int d = 1; d < 32; d <<= 1) {
        if (d >= n) break;
        float4 o = shfl_down4(v, d);
        if (lane + d < n) v = comp4(v, o);
    }
    return v;
}

struct Tile {
    float rr[ITEMS];   // r
    float dd[ITEMS];   // delta
    float a1[ITEMS];   // gamma * mask
    int   nvalid;
};

__device__ __forceinline__ void load_tile(const float* __restrict__ r,
                                          const float* __restrict__ v,
                                          const int*   __restrict__ m,
                                          long s, long B, Tile& td) {
    float vv[ITEMS + 1];
    long rem = B - s;
    td.nvalid = (rem >= ITEMS) ? ITEMS : (rem > 0 ? (int)rem : 0);
    if (td.nvalid == ITEMS) {
#pragma unroll
        for (int j = 0; j < ITEMS / 4; j++) {
            float4 x = *reinterpret_cast<const float4*>(r + s + 4 * j);
            float4 y = *reinterpret_cast<const float4*>(v + s + 4 * j);
            int4  mi = *reinterpret_cast<const int4*>(m + s + 4 * j);
            td.rr[4*j+0] = x.x; td.rr[4*j+1] = x.y; td.rr[4*j+2] = x.z; td.rr[4*j+3] = x.w;
            vv[4*j+0] = y.x; vv[4*j+1] = y.y; vv[4*j+2] = y.z; vv[4*j+3] = y.w;
            td.a1[4*j+0] = GAMMA * (float)mi.x; td.a1[4*j+1] = GAMMA * (float)mi.y;
            td.a1[4*j+2] = GAMMA * (float)mi.z; td.a1[4*j+3] = GAMMA * (float)mi.w;
        }
        vv[ITEMS] = (s + ITEMS < B) ? v[s + ITEMS] : 0.f;
    } else {
#pragma unroll
        for (int i = 0; i < ITEMS; i++) {
            if (i < td.nvalid) {
                td.rr[i] = r[s + i];
                vv[i]    = v[s + i];
                td.a1[i] = GAMMA * (float)m[s + i];
            } else { td.rr[i] = 0.f; vv[i] = 0.f; td.a1[i] = 0.f; }
        }
        vv[ITEMS] = 0.f;
    }
#pragma unroll
    for (int i = 0; i < ITEMS; i++)
        td.dd[i] = td.rr[i] + td.a1[i] * vv[i + 1] - vv[i];
}

__device__ __forceinline__ float4 tile_summary(const Tile& td) {
    float av = 1.f, bv = 0.f, aa = 1.f, ba = 0.f;
#pragma unroll
    for (int i = 0; i < ITEMS; i++) {
        if (i < td.nvalid) {
            float a1 = td.a1[i];
            float a2 = a1 * TAUF;
            bv = bv + av * td.rr[i]; av = av * a1;
            ba = ba + aa * td.dd[i]; aa = aa * a2;
        }
    }
    return make_float4(av, bv, aa, ba);
}

// ---------------- Pass 1: summaries + moments; last block fuses the carry scan + stats ----------------
__global__ void __launch_bounds__(THREADS) k_pass1(const float* __restrict__ r,
                                                   const float* __restrict__ v,
                                                   const int* __restrict__ m,
                                                   long B, int NB) {
    __shared__ float4 WAGG[NWARPS];
    __shared__ float2 WC[NWARPS];
    __shared__ float SS0[NWARPS], SS1[NWARPS], SS2[NWARPS], SS3[NWARPS], SS4[NWARPS];
    __shared__ int LASTF;
    __shared__ double DS[NWARPS], DQ[NWARPS];
    int t = threadIdx.x, lane = t & 31, w = t >> 5;
    long s = (long)blockIdx.x * CHUNK + (long)t * ITEMS;
    Tile td;
    load_tile(r, v, m, s, B, td);
    float4 f = tile_summary(td);
    float4 sfx = warp_suffix_scan(f, lane);
    if (lane == 0) WAGG[w] = sfx;
    __syncthreads();
    if (w == 0) {                               // whole warp 0
        float4 sw = (lane < NWARPS) ? WAGG[lane] : ident4();
        sw = crosswarp_suffix_scan(sw, lane, NWARPS);
        if (lane == 0) g_blk[blockIdx.x] = sw;
        float4 ex = shfl_down4(sw, 1);
        if (lane >= NWARPS - 1) ex = ident4();
        if (lane < NWARPS) WC[lane] = make_float2(ex.w, ex.z);   // (Pa, Ga) of warp
    }
    __syncthreads();
    float2 wc = WC[w];
    float4 X = shfl_down4(sfx, 1);
    if (lane == 31) X = ident4();
    // carry entering this thread's items as function of block carry c: P + G*c
    float P = X.w + X.z * wc.x;
    float G = X.z * wc.y;
    float sp = 0.f, sg = 0.f, spp = 0.f, spg = 0.f, sgg = 0.f;
#pragma unroll
    for (int i = ITEMS - 1; i >= 0; i--) {
        if (i < td.nvalid) {
            float a2 = td.a1[i] * TAUF;
            P = td.dd[i] + a2 * P;
            G = a2 * G;
            sp += P; sg += G;
            spp += P * P; spg += P * G; sgg += G * G;
        }
    }
#pragma unroll
    for (int d = 16; d > 0; d >>= 1) {
        sp  += __shfl_down_sync(0xffffffffu, sp, d);
        sg  += __shfl_down_sync(0xffffffffu, sg, d);
        spp += __shfl_down_sync(0xffffffffu, spp, d);
        spg += __shfl_down_sync(0xffffffffu, spg, d);
        sgg += __shfl_down_sync(0xffffffffu, sgg, d);
    }
    if (lane == 0) { SS0[w] = sp; SS1[w] = sg; SS2[w] = spp; SS3[w] = spg; SS4[w] = sgg; }
    __syncthreads();
    if (w == 0) {                               // whole warp 0
        bool ok = lane < NWARPS;
        float a0 = ok ? SS0[lane] : 0.f;
        float a1 = ok ? SS1[lane] : 0.f;
        float a2 = ok ? SS2[lane] : 0.f;
        float a3 = ok ? SS3[lane] : 0.f;
        float a4 = ok ? SS4[lane] : 0.f;
#pragma unroll
        for (int d = NWARPS / 2; d > 0; d >>= 1) {
            a0 += __shfl_down_sync(0xffffffffu, a0, d);
            a1 += __shfl_down_sync(0xffffffffu, a1, d);
            a2 += __shfl_down_sync(0xffffffffu, a2, d);
            a3 += __shfl_down_sync(0xffffffffu, a3, d);
            a4 += __shfl_down_sync(0xffffffffu, a4, d);
        }
        if (lane == 0) {
            g_mA[blockIdx.x] = make_float4(a0, a1, a2, a3);
            g_mB[blockIdx.x] = a4;
        }
    }
    // ---- last-done block performs the (former) pass2 inline ----
    if (t == 0) {
        __threadfence();
        unsigned int dn = atomicAdd(&g_done, 1);
        LASTF = (dn == (unsigned int)NB - 1) ? 1 : 0;
    }
    __syncthreads();
    if (!LASTF) return;
    __threadfence();                            // all other blocks' writes visible

    // Each thread composes PER consecutive block summaries (reload from L2 to keep regs low)
    int base = t * PER;
    float4 E = ident4();
#pragma unroll 1
    for (int i = 0; i < PER; i++) {
        int b = base + i;
        float4 fb = (b < NB) ? g_blk[b] : ident4();
        E = comp4(E, fb);
    }
    float4 sfx2 = warp_suffix_scan(E, lane);
    if (lane == 0) WAGG[w] = sfx2;
    __syncthreads();
    if (w == 0) {
        float4 sw = (lane < NWARPS) ? WAGG[lane] : ident4();
        sw = crosswarp_suffix_scan(sw, lane, NWARPS);
        float4 ex = shfl_down4(sw, 1);
        if (lane >= NWARPS - 1) ex = ident4();
        if (lane < NWARPS) WC[lane] = make_float2(ex.y, ex.w);   // VALUE carries (c=0)
    }
    __syncthreads();
    float2 wcar = WC[w];
    float4 X2 = shfl_down4(sfx2, 1);
    if (lane == 31) X2 = ident4();
    float2 V;                                   // carry entering block base+PER-1
    V.x = X2.y + X2.x * wcar.x;
    V.y = X2.w + X2.z * wcar.y;
    double dsum = 0.0, dssq = 0.0;
#pragma unroll 1
    for (int i = PER - 1; i >= 0; i--) {
        int b = base + i;
        if (b < NB) {
            g_carry[b] = V;
            float4 mA = g_mA[b]; float mB = g_mB[b];
            float c = V.y;
            dsum += (double)(mA.x + mA.y * c);
            dssq += (double)(mA.z + 2.f * mA.w * c + mB * c * c);
            float4 fb = g_blk[b];
            float2 nV;
            nV.x = fb.y + fb.x * V.x;
            nV.y = fb.w + fb.z * V.y;
            V = nV;
        }
    }
#pragma unroll
    for (int d = 16; d > 0; d >>= 1) {
        dsum += __shfl_down_sync(0xffffffffu, dsum, d);
        dssq += __shfl_down_sync(0xffffffffu, dssq, d);
    }
    if (lane == 0) { DS[w] = dsum; DQ[w] = dssq; }
    __syncthreads();
    if (w == 0) {
        bool ok = lane < NWARPS;
        double sd = ok ? DS[lane] : 0.0;
        double qd = ok ? DQ[lane] : 0.0;
#pragma unroll
        for (int d = NWARPS / 2; d > 0; d >>= 1) {
            sd += __shfl_down_sync(0xffffffffu, sd, d);
            qd += __shfl_down_sync(0xffffffffu, qd, d);
        }
        if (lane == 0) {
            double mean = sd / (double)B;
            double var  = (qd - sd * mean) / (double)(B - 1);
            g_normc = make_float2((float)mean, (float)(1.0 / sqrt(var)));
            g_done = 0;                         // reset for next graph replay
        }
    }
}

// ---------------- Pass 3: fixup + write v_target and NORMALIZED A ----------------
__global__ void __launch_bounds__(THREADS) k_pass3(const float* __restrict__ r,
                                                   const float* __restrict__ v,
                                                   const int* __restrict__ m,
                                                   float* __restrict__ outA,
                                                   float* __restrict__ outVT, long B) {
    __shared__ float4 WAGG[NWARPS];
    __shared__ float2 WCARRY[NWARPS];
    int t = threadIdx.x, lane = t & 31, w = t >> 5;
    long s = (long)blockIdx.x * CHUNK + (long)t * ITEMS;
    Tile td;
    load_tile(r, v, m, s, B, td);
    float2 nc = g_normc;
    float4 f = tile_summary(td);
    float4 sfx = warp_suffix_scan(f, lane);
    if (lane == 0) WAGG[w] = sfx;
    __syncthreads();
    if (w == 0) {
        float4 sw = (lane < NWARPS) ? WAGG[lane] : ident4();
        sw = crosswarp_suffix_scan(sw, lane, NWARPS);
        float4 ex = shfl_down4(sw, 1);
        if (lane >= NWARPS - 1) ex = ident4();
        float2 cb = g_carry[blockIdx.x];
        float2 wcv;
        wcv.x = ex.y + ex.x * cb.x;
        wcv.y = ex.w + ex.z * cb.y;
        if (lane < NWARPS) WCARRY[lane] = wcv;
    }
    __syncthreads();
    float2 wcar = WCARRY[w];
    float4 X = shfl_down4(sfx, 1);
    if (lane == 31) X = ident4();
    float cvt = X.y + X.x * wcar.x;
    float ca  = X.w + X.z * wcar.y;

    float mean = nc.x, istd = nc.y;
#pragma unroll
    for (int i = ITEMS - 1; i >= 0; i--) {
        if (i < td.nvalid) {
            float a1 = td.a1[i];
            float vt = td.rr[i] + a1 * cvt;
            float A  = td.dd[i] + a1 * TAUF * ca;
            td.rr[i] = vt;
            cvt = vt; ca = A;
            td.dd[i] = (A - mean) * istd;   // normalized in place
        }
    }
    if (td.nvalid == ITEMS) {
#pragma unroll
        for (int j2 = 0; j2 < ITEMS / 4; j2++) {
            *reinterpret_cast<float4*>(outA + s + 4 * j2) =
                make_float4(td.dd[4*j2+0], td.dd[4*j2+1], td.dd[4*j2+2], td.dd[4*j2+3]);
            *reinterpret_cast<float4*>(outVT + s + 4 * j2) =
                make_float4(td.rr[4*j2+0], td.rr[4*j2+1], td.rr[4*j2+2], td.rr[4*j2+3]);
        }
    } else {
        for (int i = 0; i < td.nvalid; i++) {
            outA[s + i]  = td.dd[i];
            outVT[s + i] = td.rr[i];
        }
    }
}

extern "C" void kernel_launch(void* const* d_in, const int* in_sizes, int n_in,
                              void* d_out, int out_size) {
    const float* r = (const float*)d_in[0];
    const float* v = (const float*)d_in[1];
    const int*   m = (const int*)d_in[2];
    long B = (long)in_sizes[0];
    float* outA  = (float*)d_out;
    float* outVT = outA + B;

    int NB = (int)((B + CHUNK - 1) / CHUNK);
    if (NB > NB_MAX) NB = NB_MAX;   // this problem: B=4194304 -> NB=2048

    k_pass1<<<NB, THREADS>>>(r, v, m, B, NB);
    k_pass3<<<NB, THREADS>>>(r, v, m, outA, outVT, B);
}

// round 11
// speedup vs baseline: 2.0976x; 1.2252x over previous
#include <cuda_runtime.h>
#include <math.h>

#define GAMMA 0.99f
#define TAUF  0.95f

constexpr int THREADS = 256;
constexpr int ITEMS   = 8;
constexpr int CHUNK   = THREADS * ITEMS;   // 2048
constexpr int NWARPS  = THREADS / 32;      // 8
constexpr int PER     = 8;                 // summaries per thread in fused pass2
constexpr int NB_MAX  = THREADS * PER;     // 2048 blocks max (B <= 4,194,304)

// Scratch (device globals; no allocation allowed)
__device__ float4 g_blk[NB_MAX];     // per-block affine summary: (a_vt, b_vt, a_A, b_A)
__device__ float2 g_carry[NB_MAX];   // per-block incoming carry VALUES (vt, A)
__device__ float4 g_mA[NB_MAX];      // per-block (SP, SG, SPP, SPG)
__device__ float  g_mB[NB_MAX];      // per-block SGG
__device__ unsigned char g_bits[NB_MAX * THREADS];  // packed masks, 1 byte per thread-tile
__device__ float2 g_normc;           // (mean, inv_std)
__device__ unsigned int g_done = 0;  // finish counter (reset by last block)

__device__ __forceinline__ float4 ident4() { return make_float4(1.f, 0.f, 1.f, 0.f); }

// lo covers lower (earlier) indices; carry flows high->low: result = f_lo(f_hi(c))
__device__ __forceinline__ float4 comp4(float4 lo, float4 hi) {
    float4 o;
    o.x = lo.x * hi.x;
    o.y = lo.y + lo.x * hi.y;
    o.z = lo.z * hi.z;
    o.w = lo.w + lo.z * hi.w;
    return o;
}

__device__ __forceinline__ float4 shfl_down4(float4 v, int d) {
    float4 o;
    o.x = __shfl_down_sync(0xffffffffu, v.x, d);
    o.y = __shfl_down_sync(0xffffffffu, v.y, d);
    o.z = __shfl_down_sync(0xffffffffu, v.z, d);
    o.w = __shfl_down_sync(0xffffffffu, v.w, d);
    return o;
}

// Inclusive SUFFIX scan within a warp; ALL 32 lanes execute.
__device__ __forceinline__ float4 warp_suffix_scan(float4 v, int lane) {
#pragma unroll
    for (int d = 1; d < 32; d <<= 1) {
        float4 o = shfl_down4(v, d);
        if (lane + d < 32) v = comp4(v, o);
    }
    return v;
}

__device__ __forceinline__ float4 crosswarp_suffix_scan(float4 v, int lane, int n) {
#pragma unroll
    for (int d = 1; d < 32; d <<= 1) {
        if (d >= n) break;
        float4 o = shfl_down4(v, d);
        if (lane + d < n) v = comp4(v, o);
    }
    return v;
}

// a1 coefficient for item i from the packed mask byte
__device__ __forceinline__ float a1_of(unsigned int bits, int i) {
    return ((bits >> i) & 1u) ? GAMMA : 0.f;
}

// Tile summary from (rr, vv, bits): forward composition (F = f_0 o f_1 o ...)
__device__ __forceinline__ float4 tile_summary_rv(const float* rr, const float* vv,
                                                  unsigned int bits, int nvalid) {
    float av = 1.f, bv = 0.f, aa = 1.f, ba = 0.f;
#pragma unroll
    for (int i = 0; i < ITEMS; i++) {
        if (i < nvalid) {
            float a1 = a1_of(bits, i);
            float delta = rr[i] + a1 * vv[i + 1] - vv[i];
            float a2 = a1 * TAUF;
            bv = bv + av * rr[i]; av = av * a1;
            ba = ba + aa * delta; aa = aa * a2;
        }
    }
    return make_float4(av, bv, aa, ba);
}

// ---------------- Pass 1: summaries + moments + bits; last block fuses carry scan + stats ----------------
__global__ void __launch_bounds__(THREADS) k_pass1(const float* __restrict__ r,
                                                   const float* __restrict__ v,
                                                   const int* __restrict__ m,
                                                   long B, int NB) {
    __shared__ float4 WAGG[NWARPS];
    __shared__ float2 WC[NWARPS];
    __shared__ float SS0[NWARPS], SS1[NWARPS], SS2[NWARPS], SS3[NWARPS], SS4[NWARPS];
    __shared__ int LASTF;
    __shared__ double DS[NWARPS], DQ[NWARPS];
    int t = threadIdx.x, lane = t & 31, w = t >> 5;
    long s = (long)blockIdx.x * CHUNK + (long)t * ITEMS;

    float rr[ITEMS], vv[ITEMS + 1];
    unsigned int bits = 0;
    long rem = B - s;
    int nvalid = (rem >= ITEMS) ? ITEMS : (rem > 0 ? (int)rem : 0);
    if (nvalid == ITEMS) {
#pragma unroll
        for (int j = 0; j < ITEMS / 4; j++) {
            float4 x = *reinterpret_cast<const float4*>(r + s + 4 * j);
            float4 y = *reinterpret_cast<const float4*>(v + s + 4 * j);
            int4  mi = *reinterpret_cast<const int4*>(m + s + 4 * j);
            rr[4*j+0] = x.x; rr[4*j+1] = x.y; rr[4*j+2] = x.z; rr[4*j+3] = x.w;
            vv[4*j+0] = y.x; vv[4*j+1] = y.y; vv[4*j+2] = y.z; vv[4*j+3] = y.w;
            bits |= (unsigned int)(mi.x & 1) << (4*j+0);
            bits |= (unsigned int)(mi.y & 1) << (4*j+1);
            bits |= (unsigned int)(mi.z & 1) << (4*j+2);
            bits |= (unsigned int)(mi.w & 1) << (4*j+3);
        }
        vv[ITEMS] = (s + ITEMS < B) ? v[s + ITEMS] : 0.f;
    } else {
#pragma unroll
        for (int i = 0; i < ITEMS; i++) {
            if (i < nvalid) {
                rr[i] = r[s + i];
                vv[i] = v[s + i];
                bits |= (unsigned int)(m[s + i] & 1) << i;
            } else { rr[i] = 0.f; vv[i] = 0.f; }
        }
        vv[ITEMS] = 0.f;
    }
    g_bits[blockIdx.x * THREADS + t] = (unsigned char)bits;

    float4 f = tile_summary_rv(rr, vv, bits, nvalid);
    float4 sfx = warp_suffix_scan(f, lane);
    if (lane == 0) WAGG[w] = sfx;
    __syncthreads();
    if (w == 0) {                               // whole warp 0
        float4 sw = (lane < NWARPS) ? WAGG[lane] : ident4();
        sw = crosswarp_suffix_scan(sw, lane, NWARPS);
        if (lane == 0) g_blk[blockIdx.x] = sw;
        float4 ex = shfl_down4(sw, 1);
        if (lane >= NWARPS - 1) ex = ident4();
        if (lane < NWARPS) WC[lane] = make_float2(ex.w, ex.z);   // (Pa, Ga) of warp
    }
    __syncthreads();
    float2 wc = WC[w];
    float4 X = shfl_down4(sfx, 1);
    if (lane == 31) X = ident4();
    // carry entering this thread's items as function of block carry c: P + G*c
    float P = X.w + X.z * wc.x;
    float G = X.z * wc.y;
    float sp = 0.f, sg = 0.f, spp = 0.f, spg = 0.f, sgg = 0.f;
#pragma unroll
    for (int i = ITEMS - 1; i >= 0; i--) {
        if (i < nvalid) {
            float a1 = a1_of(bits, i);
            float delta = rr[i] + a1 * vv[i + 1] - vv[i];
            float a2 = a1 * TAUF;
            P = delta + a2 * P;
            G = a2 * G;
            sp += P; sg += G;
            spp += P * P; spg += P * G; sgg += G * G;
        }
    }
#pragma unroll
    for (int d = 16; d > 0; d >>= 1) {
        sp  += __shfl_down_sync(0xffffffffu, sp, d);
        sg  += __shfl_down_sync(0xffffffffu, sg, d);
        spp += __shfl_down_sync(0xffffffffu, spp, d);
        spg += __shfl_down_sync(0xffffffffu, spg, d);
        sgg += __shfl_down_sync(0xffffffffu, sgg, d);
    }
    if (lane == 0) { SS0[w] = sp; SS1[w] = sg; SS2[w] = spp; SS3[w] = spg; SS4[w] = sgg; }
    __syncthreads();
    if (w == 0) {                               // whole warp 0
        bool ok = lane < NWARPS;
        float a0 = ok ? SS0[lane] : 0.f;
        float a1 = ok ? SS1[lane] : 0.f;
        float a2 = ok ? SS2[lane] : 0.f;
        float a3 = ok ? SS3[lane] : 0.f;
        float a4 = ok ? SS4[lane] : 0.f;
#pragma unroll
        for (int d = NWARPS / 2; d > 0; d >>= 1) {
            a0 += __shfl_down_sync(0xffffffffu, a0, d);
            a1 += __shfl_down_sync(0xffffffffu, a1, d);
            a2 += __shfl_down_sync(0xffffffffu, a2, d);
            a3 += __shfl_down_sync(0xffffffffu, a3, d);
            a4 += __shfl_down_sync(0xffffffffu, a4, d);
        }
        if (lane == 0) {
            g_mA[blockIdx.x] = make_float4(a0, a1, a2, a3);
            g_mB[blockIdx.x] = a4;
        }
    }
    // ---- last-done block performs the (former) pass2 inline ----
    if (t == 0) {
        __threadfence();
        unsigned int dn = atomicAdd(&g_done, 1);
        LASTF = (dn == (unsigned int)NB - 1) ? 1 : 0;
    }
    __syncthreads();
    if (!LASTF) return;
    __threadfence();                            // all other blocks' writes visible

    int base = t * PER;
    float4 E = ident4();
#pragma unroll 1
    for (int i = 0; i < PER; i++) {
        int b = base + i;
        float4 fb = (b < NB) ? g_blk[b] : ident4();
        E = comp4(E, fb);
    }
    float4 sfx2 = warp_suffix_scan(E, lane);
    if (lane == 0) WAGG[w] = sfx2;
    __syncthreads();
    if (w == 0) {
        float4 sw = (lane < NWARPS) ? WAGG[lane] : ident4();
        sw = crosswarp_suffix_scan(sw, lane, NWARPS);
        float4 ex = shfl_down4(sw, 1);
        if (lane >= NWARPS - 1) ex = ident4();
        if (lane < NWARPS) WC[lane] = make_float2(ex.y, ex.w);   // VALUE carries (c=0)
    }
    __syncthreads();
    float2 wcar = WC[w];
    float4 X2 = shfl_down4(sfx2, 1);
    if (lane == 31) X2 = ident4();
    float2 V;                                   // carry entering block base+PER-1
    V.x = X2.y + X2.x * wcar.x;
    V.y = X2.w + X2.z * wcar.y;
    double dsum = 0.0, dssq = 0.0;
#pragma unroll 1
    for (int i = PER - 1; i >= 0; i--) {
        int b = base + i;
        if (b < NB) {
            g_carry[b] = V;
            float4 mA = g_mA[b]; float mB = g_mB[b];
            float c = V.y;
            dsum += (double)(mA.x + mA.y * c);
            dssq += (double)(mA.z + 2.f * mA.w * c + mB * c * c);
            float4 fb = g_blk[b];
            float2 nV;
            nV.x = fb.y + fb.x * V.x;
            nV.y = fb.w + fb.z * V.y;
            V = nV;
        }
    }
#pragma unroll
    for (int d = 16; d > 0; d >>= 1) {
        dsum += __shfl_down_sync(0xffffffffu, dsum, d);
        dssq += __shfl_down_sync(0xffffffffu, dssq, d);
    }
    if (lane == 0) { DS[w] = dsum; DQ[w] = dssq; }
    __syncthreads();
    if (w == 0) {
        bool ok = lane < NWARPS;
        double sd = ok ? DS[lane] : 0.0;
        double qd = ok ? DQ[lane] : 0.0;
#pragma unroll
        for (int d = NWARPS / 2; d > 0; d >>= 1) {
            sd += __shfl_down_sync(0xffffffffu, sd, d);
            qd += __shfl_down_sync(0xffffffffu, qd, d);
        }
        if (lane == 0) {
            double mean = sd / (double)B;
            double var  = (qd - sd * mean) / (double)(B - 1);
            g_normc = make_float2((float)mean, (float)(1.0 / sqrt(var)));
            g_done = 0;                         // reset for next graph replay
        }
    }
}

// ---------------- Pass 3: fixup + write v_target and NORMALIZED A (no mask re-read) ----------------
__global__ void __launch_bounds__(THREADS, 5) k_pass3(const float* __restrict__ r,
                                                      const float* __restrict__ v,
                                                      float* __restrict__ outA,
                                                      float* __restrict__ outVT, long B) {
    __shared__ float4 WAGG[NWARPS];
    __shared__ float2 WCARRY[NWARPS];
    int t = threadIdx.x, lane = t & 31, w = t >> 5;
    long s = (long)blockIdx.x * CHUNK + (long)t * ITEMS;

    float rr[ITEMS], vv[ITEMS + 1];
    unsigned int bits = g_bits[blockIdx.x * THREADS + t];
    long rem = B - s;
    int nvalid = (rem >= ITEMS) ? ITEMS : (rem > 0 ? (int)rem : 0);
    if (nvalid == ITEMS) {
#pragma unroll
        for (int j = 0; j < ITEMS / 4; j++) {
            float4 x = *reinterpret_cast<const float4*>(r + s + 4 * j);
            float4 y = *reinterpret_cast<const float4*>(v + s + 4 * j);
            rr[4*j+0] = x.x; rr[4*j+1] = x.y; rr[4*j+2] = x.z; rr[4*j+3] = x.w;
            vv[4*j+0] = y.x; vv[4*j+1] = y.y; vv[4*j+2] = y.z; vv[4*j+3] = y.w;
        }
        vv[ITEMS] = (s + ITEMS < B) ? v[s + ITEMS] : 0.f;
    } else {
#pragma unroll
        for (int i = 0; i < ITEMS; i++) {
            if (i < nvalid) { rr[i] = r[s + i]; vv[i] = v[s + i]; }
            else { rr[i] = 0.f; vv[i] = 0.f; }
        }
        vv[ITEMS] = 0.f;
    }

    float2 nc = g_normc;
    float4 f = tile_summary_rv(rr, vv, bits, nvalid);
    float4 sfx = warp_suffix_scan(f, lane);
    if (lane == 0) WAGG[w] = sfx;
    __syncthreads();
    if (w == 0) {
        float4 sw = (lane < NWARPS) ? WAGG[lane] : ident4();
        sw = crosswarp_suffix_scan(sw, lane, NWARPS);
        float4 ex = shfl_down4(sw, 1);
        if (lane >= NWARPS - 1) ex = ident4();
        float2 cb = g_carry[blockIdx.x];
        float2 wcv;
        wcv.x = ex.y + ex.x * cb.x;
        wcv.y = ex.w + ex.z * cb.y;
        if (lane < NWARPS) WCARRY[lane] = wcv;
    }
    __syncthreads();
    float2 wcar = WCARRY[w];
    float4 X = shfl_down4(sfx, 1);
    if (lane == 31) X = ident4();
    float cvt = X.y + X.x * wcar.x;
    float ca  = X.w + X.z * wcar.y;

    float mean = nc.x, istd = nc.y;
    // fixup: vt -> rr[i], A -> vv[i+1] (vv[i+1] dead after delta_i)
#pragma unroll
    for (int i = ITEMS - 1; i >= 0; i--) {
        if (i < nvalid) {
            float a1 = a1_of(bits, i);
            float delta = rr[i] + a1 * vv[i + 1] - vv[i];
            float vt = rr[i] + a1 * cvt;
            float A  = delta + a1 * TAUF * ca;
            rr[i] = vt;
            vv[i + 1] = A;
            cvt = vt; ca = A;
        }
    }
    if (nvalid == ITEMS) {
        *reinterpret_cast<float4*>(outVT + s) = make_float4(rr[0], rr[1], rr[2], rr[3]);
        *reinterpret_cast<float4*>(outVT + s + 4) = make_float4(rr[4], rr[5], rr[6], rr[7]);
        *reinterpret_cast<float4*>(outA + s) =
            make_float4((vv[1] - mean) * istd, (vv[2] - mean) * istd,
                        (vv[3] - mean) * istd, (vv[4] - mean) * istd);
        *reinterpret_cast<float4*>(outA + s + 4) =
            make_float4((vv[5] - mean) * istd, (vv[6] - mean) * istd,
                        (vv[7] - mean) * istd, (vv[8] - mean) * istd);
    } else {
#pragma unroll
        for (int i = 0; i < ITEMS; i++) {
            if (i < nvalid) {
                outVT[s + i] = rr[i];
                outA[s + i]  = (vv[i + 1] - mean) * istd;
            }
        }
    }
}

extern "C" void kernel_launch(void* const* d_in, const int* in_sizes, int n_in,
                              void* d_out, int out_size) {
    const float* r = (const float*)d_in[0];
    const float* v = (const float*)d_in[1];
    const int*   m = (const int*)d_in[2];
    long B = (long)in_sizes[0];
    float* outA  = (float*)d_out;
    float* outVT = outA + B;

    int NB = (int)((B + CHUNK - 1) / CHUNK);
    if (NB > NB_MAX) NB = NB_MAX;   // this problem: B=4194304 -> NB=2048

    k_pass1<<<NB, THREADS>>>(r, v, m, B, NB);
    k_pass3<<<NB, THREADS>>>(r, v, outA, outVT, B);
}